// round 13
// baseline (speedup 1.0000x reference)
#include <cuda_runtime.h>
#include <cuda_bf16.h>
#include <cstdint>

#define D 64
#define MAXN 50176

// Scratch (static device globals — allocation-free). Referenced ONLY in
// device code (host-side symbol is an ATS-readable shadow — Round-2 bug).
__device__ float g_agg[MAXN * D];    // sum over dst of (h1[src] + e1)
__device__ float g_deg[MAXN];
__device__ float g_h1[MAXN * D];     // X @ Wn2n_u
__device__ float g_hu2[MAXN * D];    // X @ (W_n2e_u @ W_e2e_bot)
__device__ float g_hv2[MAXN * D];    // [S,X] @ (W_n2e_v @ W_e2e_bot)
__device__ float g_Wcu[D * D];
__device__ float g_Wcv[2 * D * D];
// tf32 B fragments, 2 sets: [0:4096) We2e_top, [4096:8192) We2n
// layout per set: [kstep 8][ntile 8][lane 32][2]
__device__ float g_Wmma[2 * 8 * 8 * 32 * 2];

// ---------------------------------------------------------------------------
__global__ void k_zero(int N) {
    int i = blockIdx.x * blockDim.x + threadIdx.x;
    int nv = N * D / 4;
    if (i < nv)
        reinterpret_cast<float4*>(g_agg)[i] = make_float4(0.f, 0.f, 0.f, 0.f);
    if (i < N) g_deg[i] = 0.0f;
}

// ---------------------------------------------------------------------------
// K0b: composite weights Wcu, Wcv + tf32 fragments of We2e_top and We2n
// ---------------------------------------------------------------------------
__global__ void k_wprep(const float* __restrict__ Wn2e_u,
                        const float* __restrict__ Wn2e_v,
                        const float* __restrict__ We2e,
                        const float* __restrict__ We2n) {
    int idx = blockIdx.x * blockDim.x + threadIdx.x;
    if (idx < D * D) {
        int r = idx >> 6, j = idx & 63;
        float s = 0.0f;
        #pragma unroll 8
        for (int t = 0; t < D; t++)
            s += __ldg(Wn2e_u + r * D + t) * __ldg(We2e + (D + t) * D + j);
        g_Wcu[idx] = s;
    } else if (idx < 3 * D * D) {
        int i2 = idx - D * D;
        int r = i2 >> 6, j = i2 & 63;
        float s = 0.0f;
        #pragma unroll 8
        for (int t = 0; t < D; t++)
            s += __ldg(Wn2e_v + r * D + t) * __ldg(We2e + (D + t) * D + j);
        g_Wcv[i2] = s;
    } else if (idx < 3 * D * D + 2 * 2048) {
        int i = idx - 3 * D * D;               // 0..4095
        int set = i >> 11;                     // 0: We2e_top, 1: We2n
        int j = i & 2047;
        int lane = j & 31, nt = (j >> 5) & 7, ks = j >> 8;
        int gid = lane >> 2, tig = lane & 3;
        const float* W = set ? We2n : We2e;    // We2e rows 0..63 = top
        float w0 = W[(ks * 8 + tig) * D + nt * 8 + gid];
        float w1 = W[(ks * 8 + tig + 4) * D + nt * 8 + gid];
        uint32_t t0, t1;
        asm("cvt.rna.tf32.f32 %0, %1;" : "=r"(t0) : "f"(w0));
        asm("cvt.rna.tf32.f32 %0, %1;" : "=r"(t1) : "f"(w1));
        g_Wmma[i * 2 + 0] = __uint_as_float(t0);
        g_Wmma[i * 2 + 1] = __uint_as_float(t1);
    }
}

// ---------------------------------------------------------------------------
// Tile loader: 64 rows x 64 feats transposed (node kernels)
// ---------------------------------------------------------------------------
__device__ __forceinline__ void load_tile_T(float (*sT)[65],
                                            const float* __restrict__ p,
                                            int base, int nRows, int tid) {
    for (int i = tid; i < 64 * 16; i += 256) {
        int n = i >> 4, q = i & 15;
        float4 v = (n < nRows)
            ? reinterpret_cast<const float4*>(p)[(size_t)(base + n) * 16 + q]
            : make_float4(0.f, 0.f, 0.f, 0.f);
        sT[4 * q + 0][n] = v.x;
        sT[4 * q + 1][n] = v.y;
        sT[4 * q + 2][n] = v.z;
        sT[4 * q + 3][n] = v.w;
    }
}

// ---------------------------------------------------------------------------
// K1: node precompute  h1 = X@Wu,  hu2 = X@Wcu,  hv2 = S@WcvS + X@WcvX
// ---------------------------------------------------------------------------
__global__ __launch_bounds__(256) void k_node_pre(const float* __restrict__ S,
                                                  const float* __restrict__ X,
                                                  const float* __restrict__ Wu,
                                                  int N) {
    extern __shared__ float sm[];
    float (*sXT)[65] = (float(*)[65])sm;              // 4160
    float (*sST)[65] = (float(*)[65])(sm + 4160);     // 4160
    float* sWcu  = sm + 8320;                          // 4096
    float* sWcvS = sm + 12416;                         // 4096
    float* sWcvX = sm + 16512;                         // 4096
    float* sWu   = sm + 20608;                         // 4096 -> 24704 total

    int tid = threadIdx.x;
    int base = blockIdx.x * 64;
    int nN = N - base; if (nN > 64) nN = 64;

    for (int i = tid; i < D * D; i += 256) {
        sWcu[i]  = g_Wcu[i];
        sWcvS[i] = g_Wcv[i];
        sWcvX[i] = g_Wcv[D * D + i];
        sWu[i]   = Wu[i];
    }
    load_tile_T(sXT, X, base, nN, tid);
    load_tile_T(sST, S, base, nN, tid);
    __syncthreads();

    int tx = tid & 15, ty = tid >> 4;
    float accU[4][4] = {}, accV[4][4] = {}, accH[4][4] = {};
    #pragma unroll 8
    for (int k = 0; k < D; k++) {
        float x0 = sXT[k][ty * 4 + 0], x1 = sXT[k][ty * 4 + 1];
        float x2 = sXT[k][ty * 4 + 2], x3 = sXT[k][ty * 4 + 3];
        float s0 = sST[k][ty * 4 + 0], s1 = sST[k][ty * 4 + 1];
        float s2 = sST[k][ty * 4 + 2], s3 = sST[k][ty * 4 + 3];
        float4 bu = *reinterpret_cast<const float4*>(&sWcu[k * D + tx * 4]);
        float4 bs = *reinterpret_cast<const float4*>(&sWcvS[k * D + tx * 4]);
        float4 bx = *reinterpret_cast<const float4*>(&sWcvX[k * D + tx * 4]);
        float4 bh = *reinterpret_cast<const float4*>(&sWu[k * D + tx * 4]);
        accU[0][0] += x0*bu.x; accU[0][1] += x0*bu.y; accU[0][2] += x0*bu.z; accU[0][3] += x0*bu.w;
        accU[1][0] += x1*bu.x; accU[1][1] += x1*bu.y; accU[1][2] += x1*bu.z; accU[1][3] += x1*bu.w;
        accU[2][0] += x2*bu.x; accU[2][1] += x2*bu.y; accU[2][2] += x2*bu.z; accU[2][3] += x2*bu.w;
        accU[3][0] += x3*bu.x; accU[3][1] += x3*bu.y; accU[3][2] += x3*bu.z; accU[3][3] += x3*bu.w;
        accH[0][0] += x0*bh.x; accH[0][1] += x0*bh.y; accH[0][2] += x0*bh.z; accH[0][3] += x0*bh.w;
        accH[1][0] += x1*bh.x; accH[1][1] += x1*bh.y; accH[1][2] += x1*bh.z; accH[1][3] += x1*bh.w;
        accH[2][0] += x2*bh.x; accH[2][1] += x2*bh.y; accH[2][2] += x2*bh.z; accH[2][3] += x2*bh.w;
        accH[3][0] += x3*bh.x; accH[3][1] += x3*bh.y; accH[3][2] += x3*bh.z; accH[3][3] += x3*bh.w;
        accV[0][0] += s0*bs.x + x0*bx.x; accV[0][1] += s0*bs.y + x0*bx.y;
        accV[0][2] += s0*bs.z + x0*bx.z; accV[0][3] += s0*bs.w + x0*bx.w;
        accV[1][0] += s1*bs.x + x1*bx.x; accV[1][1] += s1*bs.y + x1*bx.y;
        accV[1][2] += s1*bs.z + x1*bx.z; accV[1][3] += s1*bs.w + x1*bx.w;
        accV[2][0] += s2*bs.x + x2*bx.x; accV[2][1] += s2*bs.y + x2*bx.y;
        accV[2][2] += s2*bs.z + x2*bx.z; accV[2][3] += s2*bs.w + x2*bx.w;
        accV[3][0] += s3*bs.x + x3*bx.x; accV[3][1] += s3*bs.y + x3*bx.y;
        accV[3][2] += s3*bs.z + x3*bx.z; accV[3][3] += s3*bs.w + x3*bx.w;
    }

    #pragma unroll
    for (int r = 0; r < 4; r++) {
        int n = ty * 4 + r;
        if (n >= nN) continue;
        size_t o = (size_t)(base + n) * 16 + tx;
        reinterpret_cast<float4*>(g_hu2)[o] =
            make_float4(accU[r][0], accU[r][1], accU[r][2], accU[r][3]);
        reinterpret_cast<float4*>(g_hv2)[o] =
            make_float4(accV[r][0], accV[r][1], accV[r][2], accV[r][3]);
        reinterpret_cast<float4*>(g_h1)[o] =
            make_float4(accH[r][0], accH[r][1], accH[r][2], accH[r][3]);
    }
}

// ---------------------------------------------------------------------------
// K_edge v9: dual tf32 mma, weights via __ldg (L1-resident — no smem weight
// load, no in-loop LDS for B), single staging phase into double sOut, then
// ONE fused final pass doing scatter + epilogue. 2 syncthreads total.
// ---------------------------------------------------------------------------
#define SE_PITCH 68
#define SO_PITCH 72
__global__ __launch_bounds__(256)
void k_edge(const float* __restrict__ edge_in,
            const int* __restrict__ src,
            const int* __restrict__ dst,
            const float* __restrict__ bias_e,
            float* __restrict__ e_out,
            int E) {
    extern __shared__ float sm[];
    float* sE    = sm;                          // 64*68 = 4352 floats
    float* sOut0 = sm + 64 * SE_PITCH;          // 64*72 = 4608 (e_out acc)
    float* sOut1 = sOut0 + 64 * SO_PITCH;       // 64*72 = 4608 (e1 acc)
    int* sSrc = (int*)(sOut1 + 64 * SO_PITCH);  // 64
    int* sDst = sSrc + 64;                      // 64

    int tid = threadIdx.x;
    int ebase = blockIdx.x * 64;
    int nE = E - ebase; if (nE > 64) nE = 64;

    // edge tile (64 x 64), edge-major
    #pragma unroll
    for (int it = 0; it < 4; it++) {
        int i = tid + it * 256;
        int e = i >> 4, q = i & 15;
        float4 v = (e < nE)
            ? reinterpret_cast<const float4*>(edge_in)[(size_t)(ebase + e) * 16 + q]
            : make_float4(0.f, 0.f, 0.f, 0.f);
        *reinterpret_cast<float4*>(&sE[e * SE_PITCH + 4 * q]) = v;
    }
    if (tid < 64) {
        sSrc[tid] = (tid < nE) ? src[ebase + tid] : 0;
        sDst[tid] = (tid < nE) ? dst[ebase + tid] : 0;
    }
    __syncthreads();

    if (tid < 64 && tid < nE) atomicAdd(g_deg + sDst[tid], 1.0f);

    int wid = tid >> 5, lane = tid & 31;
    int gid = lane >> 2, tig = lane & 3;
    int mw = wid & 3;            // m-tile (16 edges)
    int nhalf = wid >> 2;        // 0: n 0..31, 1: n 32..63
    int ew = mw * 16;

    // ---- dual tf32 mma: acc (e_out via We2e_top), acc2 (e1 via We2n) ----
    float acc[4][4], acc2[4][4];
    #pragma unroll
    for (int nt = 0; nt < 4; nt++) {
        acc[nt][0] = 0.f; acc[nt][1] = 0.f; acc[nt][2] = 0.f; acc[nt][3] = 0.f;
        acc2[nt][0] = 0.f; acc2[nt][1] = 0.f; acc2[nt][2] = 0.f; acc2[nt][3] = 0.f;
    }

    const float* rowA0 = &sE[(ew + gid) * SE_PITCH];
    const float* rowA1 = &sE[(ew + gid + 8) * SE_PITCH];
    const float2* gW = reinterpret_cast<const float2*>(g_Wmma);
    #pragma unroll
    for (int ks = 0; ks < 8; ks++) {
        int k0 = ks * 8 + tig;
        uint32_t a0, a1, a2, a3;
        asm("cvt.rna.tf32.f32 %0, %1;" : "=r"(a0) : "f"(rowA0[k0]));
        asm("cvt.rna.tf32.f32 %0, %1;" : "=r"(a1) : "f"(rowA1[k0]));
        asm("cvt.rna.tf32.f32 %0, %1;" : "=r"(a2) : "f"(rowA0[k0 + 4]));
        asm("cvt.rna.tf32.f32 %0, %1;" : "=r"(a3) : "f"(rowA1[k0 + 4]));
        #pragma unroll
        for (int nt = 0; nt < 4; nt++) {
            int ntile = nhalf * 4 + nt;
            int off = (ks * 8 + ntile) * 32 + lane;
            float2 b = __ldg(gW + off);
            uint32_t b0 = __float_as_uint(b.x), b1 = __float_as_uint(b.y);
            asm volatile(
                "mma.sync.aligned.m16n8k8.row.col.f32.tf32.tf32.f32 "
                "{%0,%1,%2,%3}, {%4,%5,%6,%7}, {%8,%9}, {%0,%1,%2,%3};"
                : "+f"(acc[nt][0]), "+f"(acc[nt][1]),
                  "+f"(acc[nt][2]), "+f"(acc[nt][3])
                : "r"(a0), "r"(a1), "r"(a2), "r"(a3), "r"(b0), "r"(b1));
            float2 c = __ldg(gW + 2048 + off);
            uint32_t c0 = __float_as_uint(c.x), c1 = __float_as_uint(c.y);
            asm volatile(
                "mma.sync.aligned.m16n8k8.row.col.f32.tf32.tf32.f32 "
                "{%0,%1,%2,%3}, {%4,%5,%6,%7}, {%8,%9}, {%0,%1,%2,%3};"
                : "+f"(acc2[nt][0]), "+f"(acc2[nt][1]),
                  "+f"(acc2[nt][2]), "+f"(acc2[nt][3])
                : "r"(a0), "r"(a1), "r"(a2), "r"(a3), "r"(c0), "r"(c1));
        }
    }

    // stage both accumulators (fragment layout, pitch 72 -> ~2-way max)
    {
        int e0 = ew + gid, e1r = ew + gid + 8;
        #pragma unroll
        for (int nt = 0; nt < 4; nt++) {
            int n = (nhalf * 4 + nt) * 8 + 2 * tig;
            *reinterpret_cast<float2*>(&sOut0[e0 * SO_PITCH + n]) =
                make_float2(acc[nt][0], acc[nt][1]);
            *reinterpret_cast<float2*>(&sOut0[e1r * SO_PITCH + n]) =
                make_float2(acc[nt][2], acc[nt][3]);
            *reinterpret_cast<float2*>(&sOut1[e0 * SO_PITCH + n]) =
                make_float2(acc2[nt][0], acc2[nt][1]);
            *reinterpret_cast<float2*>(&sOut1[e1r * SO_PITCH + n]) =
                make_float2(acc2[nt][2], acc2[nt][3]);
        }
    }
    __syncthreads();

    // ---- fused final pass: scatter RED(h1[src]+e1) + coalesced epilogue ----
    const float4* b4  = reinterpret_cast<const float4*>(bias_e);
    const float4* h14 = reinterpret_cast<const float4*>(g_h1);
    const float4* hu4 = reinterpret_cast<const float4*>(g_hu2);
    const float4* hv4 = reinterpret_cast<const float4*>(g_hv2);
    #pragma unroll
    for (int it = 0; it < 4; it++) {
        int i = tid + it * 256;
        int e = i >> 4, q = i & 15;
        if (e < nE) {
            int s = sSrc[e], d2 = sDst[e];
            // scatter: g_agg[dst] += h1[src] + e1
            float4 e1v = *reinterpret_cast<const float4*>(&sOut1[e * SO_PITCH + 4 * q]);
            float4 h1v = __ldg(h14 + (size_t)s * 16 + q);
            float* a = g_agg + (size_t)d2 * D + q * 4;
            asm volatile("red.global.add.v4.f32 [%0], {%1,%2,%3,%4};"
                         :: "l"(a),
                            "f"(h1v.x + e1v.x), "f"(h1v.y + e1v.y),
                            "f"(h1v.z + e1v.z), "f"(h1v.w + e1v.w)
                         : "memory");
            // epilogue: e_out = acc + hu2[src] + hv2[dst] + bias
            float4 av = *reinterpret_cast<const float4*>(&sOut0[e * SO_PITCH + 4 * q]);
            float4 hu = __ldg(hu4 + (size_t)s  * 16 + q);
            float4 hv = __ldg(hv4 + (size_t)d2 * 16 + q);
            float4 bb = __ldg(b4 + q);
            reinterpret_cast<float4*>(e_out)[(size_t)(ebase + e) * 16 + q] =
                make_float4(av.x + hu.x + hv.x + bb.x, av.y + hu.y + hv.y + bb.y,
                            av.z + hu.z + hv.z + bb.z, av.w + hu.w + hv.w + bb.w);
        }
    }
}

// ---------------------------------------------------------------------------
// K2: single-phase — hn comes straight from g_agg/deg:
//     h_out = S@Wv0 + X@Wv1 + (g_agg/max(deg,1))@Wv2 + bias_n
// ---------------------------------------------------------------------------
__global__ __launch_bounds__(256) void k_node_out(const float* __restrict__ S,
                                                  const float* __restrict__ X,
                                                  const float* __restrict__ Wv,
                                                  const float* __restrict__ bias_n,
                                                  float* __restrict__ h_out,
                                                  int N) {
    extern __shared__ float sm[];
    float (*sST)[65] = (float(*)[65])sm;                // 0..4160
    float (*sXT)[65] = (float(*)[65])(sm + 4160);       // ..8320
    float (*sHT)[65] = (float(*)[65])(sm + 8320);       // ..12480
    float* sWv = sm + 12480;                             // ..24768

    int tid = threadIdx.x;
    int base = blockIdx.x * 64;
    int nN = N - base; if (nN > 64) nN = 64;
    int tx = tid & 15, ty = tid >> 4;

    for (int i = tid; i < 3 * D * D; i += 256)
        sWv[i] = Wv[i];
    load_tile_T(sST, S, base, nN, tid);
    load_tile_T(sXT, X, base, nN, tid);
    // hn tile: load g_agg scaled by 1/max(deg,1), transposed
    #pragma unroll
    for (int it = 0; it < 4; it++) {
        int i = tid + it * 256;
        int n = i >> 4, q = i & 15;
        float4 v = make_float4(0.f, 0.f, 0.f, 0.f);
        if (n < nN) {
            v = reinterpret_cast<const float4*>(g_agg)[(size_t)(base + n) * 16 + q];
            float inv = 1.0f / fmaxf(g_deg[base + n], 1.0f);
            v.x *= inv; v.y *= inv; v.z *= inv; v.w *= inv;
        }
        sHT[4 * q + 0][n] = v.x;
        sHT[4 * q + 1][n] = v.y;
        sHT[4 * q + 2][n] = v.z;
        sHT[4 * q + 3][n] = v.w;
    }
    __syncthreads();

    float4 bb = reinterpret_cast<const float4*>(bias_n)[tx];
    float acc[4][4];
    #pragma unroll
    for (int r = 0; r < 4; r++) {
        acc[r][0] = bb.x; acc[r][1] = bb.y; acc[r][2] = bb.z; acc[r][3] = bb.w;
    }

    #pragma unroll 8
    for (int k = 0; k < D; k++) {
        float4 wS = *reinterpret_cast<const float4*>(&sWv[k * D + tx * 4]);
        float4 wX = *reinterpret_cast<const float4*>(&sWv[(D + k) * D + tx * 4]);
        float4 wH = *reinterpret_cast<const float4*>(&sWv[(2 * D + k) * D + tx * 4]);
        #pragma unroll
        for (int r = 0; r < 4; r++) {
            float s = sST[k][ty * 4 + r];
            float x = sXT[k][ty * 4 + r];
            float h = sHT[k][ty * 4 + r];
            acc[r][0] += s * wS.x + x * wX.x + h * wH.x;
            acc[r][1] += s * wS.y + x * wX.y + h * wH.y;
            acc[r][2] += s * wS.z + x * wX.z + h * wH.z;
            acc[r][3] += s * wS.w + x * wX.w + h * wH.w;
        }
    }

    #pragma unroll
    for (int r = 0; r < 4; r++) {
        int n = ty * 4 + r;
        if (n >= nN) continue;
        reinterpret_cast<float4*>(h_out)[(size_t)(base + n) * 16 + tx] =
            make_float4(acc[r][0], acc[r][1], acc[r][2], acc[r][3]);
    }
}

// ---------------------------------------------------------------------------
extern "C" void kernel_launch(void* const* d_in, const int* in_sizes, int n_in,
                              void* d_out, int out_size) {
    const float* S      = (const float*)d_in[0];
    const float* X      = (const float*)d_in[1];
    const float* Ein    = (const float*)d_in[2];
    const int*   src    = (const int*)d_in[3];
    const int*   dst    = (const int*)d_in[4];
    const float* Wn2n_u = (const float*)d_in[5];
    const float* Wn2n_v = (const float*)d_in[6];
    const float* We2n   = (const float*)d_in[7];
    const float* bias_n = (const float*)d_in[8];
    const float* Wn2e_u = (const float*)d_in[9];
    const float* Wn2e_v = (const float*)d_in[10];
    const float* We2e   = (const float*)d_in[11];
    const float* bias_e = (const float*)d_in[12];

    int N = in_sizes[1] / D;
    int E = in_sizes[3];
    float* h_out = (float*)d_out;
    float* e_out = h_out + (size_t)N * D;

    const int SM_PRE  = 24704 * 4;                                   // 98816 B
    const int SM_OUT  = 24768 * 4;                                   // 99072 B
    const int SM_EDGE = (64 * SE_PITCH + 2 * 64 * SO_PITCH) * 4
                        + 128 * 4;                                   // 54784 B

    cudaFuncSetAttribute(k_node_pre, cudaFuncAttributeMaxDynamicSharedMemorySize, SM_PRE);
    cudaFuncSetAttribute(k_node_out, cudaFuncAttributeMaxDynamicSharedMemorySize, SM_OUT);
    cudaFuncSetAttribute(k_edge,     cudaFuncAttributeMaxDynamicSharedMemorySize, SM_EDGE);

    int nBlk = (N + 63) / 64;
    k_zero<<<(N * D / 4 + 255) / 256, 256>>>(N);
    k_wprep<<<(3 * D * D + 2 * 2048 + 255) / 256, 256>>>(Wn2e_u, Wn2e_v, We2e, We2n);
    k_node_pre<<<nBlk, 256, SM_PRE>>>(S, X, Wn2n_u, N);
    k_edge<<<(E + 63) / 64, 256, SM_EDGE>>>(Ein, src, dst, bias_e, e_out, E);
    k_node_out<<<nBlk, 256, SM_OUT>>>(S, X, Wn2n_v, bias_n, h_out, N);
}

// round 14
// speedup vs baseline: 1.4245x; 1.4245x over previous
#include <cuda_runtime.h>
#include <cuda_bf16.h>
#include <cstdint>

#define D 64
#define MAXN 50176

// Scratch (static device globals — allocation-free). Referenced ONLY in
// device code (host-side symbol is an ATS-readable shadow — Round-2 bug).
__device__ float g_agg[MAXN * D];    // sum over dst of (h1[src] + e1)
__device__ float g_deg[MAXN];
__device__ float g_h1[MAXN * D];     // X @ Wn2n_u
__device__ float g_hu2[MAXN * D];    // X @ (W_n2e_u @ W_e2e_bot)
__device__ float g_hv2[MAXN * D];    // [S,X] @ (W_n2e_v @ W_e2e_bot)
__device__ float g_Wcu[D * D];
__device__ float g_Wcv[2 * D * D];
// tf32 B fragments, 2 sets: [0:4096) We2e_top, [4096:8192) We2n
// layout per set: [kstep 8][ntile 8][lane 32][2]
__device__ float g_Wmma[2 * 8 * 8 * 32 * 2];

// ---------------------------------------------------------------------------
__global__ void k_zero(int N) {
    int i = blockIdx.x * blockDim.x + threadIdx.x;
    int nv = N * D / 4;
    if (i < nv)
        reinterpret_cast<float4*>(g_agg)[i] = make_float4(0.f, 0.f, 0.f, 0.f);
    if (i < N) g_deg[i] = 0.0f;
}

// ---------------------------------------------------------------------------
// K0b: composite weights Wcu, Wcv + tf32 fragments of We2e_top and We2n
// ---------------------------------------------------------------------------
__global__ void k_wprep(const float* __restrict__ Wn2e_u,
                        const float* __restrict__ Wn2e_v,
                        const float* __restrict__ We2e,
                        const float* __restrict__ We2n) {
    int idx = blockIdx.x * blockDim.x + threadIdx.x;
    if (idx < D * D) {
        int r = idx >> 6, j = idx & 63;
        float s = 0.0f;
        #pragma unroll 8
        for (int t = 0; t < D; t++)
            s += __ldg(Wn2e_u + r * D + t) * __ldg(We2e + (D + t) * D + j);
        g_Wcu[idx] = s;
    } else if (idx < 3 * D * D) {
        int i2 = idx - D * D;
        int r = i2 >> 6, j = i2 & 63;
        float s = 0.0f;
        #pragma unroll 8
        for (int t = 0; t < D; t++)
            s += __ldg(Wn2e_v + r * D + t) * __ldg(We2e + (D + t) * D + j);
        g_Wcv[i2] = s;
    } else if (idx < 3 * D * D + 2 * 2048) {
        int i = idx - 3 * D * D;               // 0..4095
        int set = i >> 11;                     // 0: We2e_top, 1: We2n
        int j = i & 2047;
        int lane = j & 31, nt = (j >> 5) & 7, ks = j >> 8;
        int gid = lane >> 2, tig = lane & 3;
        const float* W = set ? We2n : We2e;    // We2e rows 0..63 = top
        float w0 = W[(ks * 8 + tig) * D + nt * 8 + gid];
        float w1 = W[(ks * 8 + tig + 4) * D + nt * 8 + gid];
        uint32_t t0, t1;
        asm("cvt.rna.tf32.f32 %0, %1;" : "=r"(t0) : "f"(w0));
        asm("cvt.rna.tf32.f32 %0, %1;" : "=r"(t1) : "f"(w1));
        g_Wmma[i * 2 + 0] = __uint_as_float(t0);
        g_Wmma[i * 2 + 1] = __uint_as_float(t1);
    }
}

// ---------------------------------------------------------------------------
// Tile loader: 64 rows x 64 feats transposed (node kernels)
// ---------------------------------------------------------------------------
__device__ __forceinline__ void load_tile_T(float (*sT)[65],
                                            const float* __restrict__ p,
                                            int base, int nRows, int tid) {
    for (int i = tid; i < 64 * 16; i += 256) {
        int n = i >> 4, q = i & 15;
        float4 v = (n < nRows)
            ? reinterpret_cast<const float4*>(p)[(size_t)(base + n) * 16 + q]
            : make_float4(0.f, 0.f, 0.f, 0.f);
        sT[4 * q + 0][n] = v.x;
        sT[4 * q + 1][n] = v.y;
        sT[4 * q + 2][n] = v.z;
        sT[4 * q + 3][n] = v.w;
    }
}

// ---------------------------------------------------------------------------
// K1: node precompute  h1 = X@Wu,  hu2 = X@Wcu,  hv2 = S@WcvS + X@WcvX
// ---------------------------------------------------------------------------
__global__ __launch_bounds__(256) void k_node_pre(const float* __restrict__ S,
                                                  const float* __restrict__ X,
                                                  const float* __restrict__ Wu,
                                                  int N) {
    extern __shared__ float sm[];
    float (*sXT)[65] = (float(*)[65])sm;              // 4160
    float (*sST)[65] = (float(*)[65])(sm + 4160);     // 4160
    float* sWcu  = sm + 8320;                          // 4096
    float* sWcvS = sm + 12416;                         // 4096
    float* sWcvX = sm + 16512;                         // 4096
    float* sWu   = sm + 20608;                         // 4096 -> 24704 total

    int tid = threadIdx.x;
    int base = blockIdx.x * 64;
    int nN = N - base; if (nN > 64) nN = 64;

    for (int i = tid; i < D * D; i += 256) {
        sWcu[i]  = g_Wcu[i];
        sWcvS[i] = g_Wcv[i];
        sWcvX[i] = g_Wcv[D * D + i];
        sWu[i]   = Wu[i];
    }
    load_tile_T(sXT, X, base, nN, tid);
    load_tile_T(sST, S, base, nN, tid);
    __syncthreads();

    int tx = tid & 15, ty = tid >> 4;
    float accU[4][4] = {}, accV[4][4] = {}, accH[4][4] = {};
    #pragma unroll 8
    for (int k = 0; k < D; k++) {
        float x0 = sXT[k][ty * 4 + 0], x1 = sXT[k][ty * 4 + 1];
        float x2 = sXT[k][ty * 4 + 2], x3 = sXT[k][ty * 4 + 3];
        float s0 = sST[k][ty * 4 + 0], s1 = sST[k][ty * 4 + 1];
        float s2 = sST[k][ty * 4 + 2], s3 = sST[k][ty * 4 + 3];
        float4 bu = *reinterpret_cast<const float4*>(&sWcu[k * D + tx * 4]);
        float4 bs = *reinterpret_cast<const float4*>(&sWcvS[k * D + tx * 4]);
        float4 bx = *reinterpret_cast<const float4*>(&sWcvX[k * D + tx * 4]);
        float4 bh = *reinterpret_cast<const float4*>(&sWu[k * D + tx * 4]);
        accU[0][0] += x0*bu.x; accU[0][1] += x0*bu.y; accU[0][2] += x0*bu.z; accU[0][3] += x0*bu.w;
        accU[1][0] += x1*bu.x; accU[1][1] += x1*bu.y; accU[1][2] += x1*bu.z; accU[1][3] += x1*bu.w;
        accU[2][0] += x2*bu.x; accU[2][1] += x2*bu.y; accU[2][2] += x2*bu.z; accU[2][3] += x2*bu.w;
        accU[3][0] += x3*bu.x; accU[3][1] += x3*bu.y; accU[3][2] += x3*bu.z; accU[3][3] += x3*bu.w;
        accH[0][0] += x0*bh.x; accH[0][1] += x0*bh.y; accH[0][2] += x0*bh.z; accH[0][3] += x0*bh.w;
        accH[1][0] += x1*bh.x; accH[1][1] += x1*bh.y; accH[1][2] += x1*bh.z; accH[1][3] += x1*bh.w;
        accH[2][0] += x2*bh.x; accH[2][1] += x2*bh.y; accH[2][2] += x2*bh.z; accH[2][3] += x2*bh.w;
        accH[3][0] += x3*bh.x; accH[3][1] += x3*bh.y; accH[3][2] += x3*bh.z; accH[3][3] += x3*bh.w;
        accV[0][0] += s0*bs.x + x0*bx.x; accV[0][1] += s0*bs.y + x0*bx.y;
        accV[0][2] += s0*bs.z + x0*bx.z; accV[0][3] += s0*bs.w + x0*bx.w;
        accV[1][0] += s1*bs.x + x1*bx.x; accV[1][1] += s1*bs.y + x1*bx.y;
        accV[1][2] += s1*bs.z + x1*bx.z; accV[1][3] += s1*bs.w + x1*bx.w;
        accV[2][0] += s2*bs.x + x2*bx.x; accV[2][1] += s2*bs.y + x2*bx.y;
        accV[2][2] += s2*bs.z + x2*bx.z; accV[2][3] += s2*bs.w + x2*bx.w;
        accV[3][0] += s3*bs.x + x3*bx.x; accV[3][1] += s3*bs.y + x3*bx.y;
        accV[3][2] += s3*bs.z + x3*bx.z; accV[3][3] += s3*bs.w + x3*bx.w;
    }

    #pragma unroll
    for (int r = 0; r < 4; r++) {
        int n = ty * 4 + r;
        if (n >= nN) continue;
        size_t o = (size_t)(base + n) * 16 + tx;
        reinterpret_cast<float4*>(g_hu2)[o] =
            make_float4(accU[r][0], accU[r][1], accU[r][2], accU[r][3]);
        reinterpret_cast<float4*>(g_hv2)[o] =
            make_float4(accV[r][0], accV[r][1], accV[r][2], accV[r][3]);
        reinterpret_cast<float4*>(g_h1)[o] =
            make_float4(accH[r][0], accH[r][1], accH[r][2], accH[r][3]);
    }
}

// ---------------------------------------------------------------------------
// K_edge v10: dual tf32 mma with SMEM weights (R12 inner loop — the proven
// one; R13's in-loop __ldg weights regressed), single staging phase into
// sOut0/sOut1 ALIASED over the dead sB region, then ONE fused final pass
// doing scatter RED(h1[src]+e1) + epilogue with direct coalesced gathers.
// 3 syncthreads. smem 54.8KB -> 4 CTAs/SM.
// ---------------------------------------------------------------------------
#define SE_PITCH 68
#define SO_PITCH 72
__global__ __launch_bounds__(256)
void k_edge(const float* __restrict__ edge_in,
            const int* __restrict__ src,
            const int* __restrict__ dst,
            const float* __restrict__ bias_e,
            float* __restrict__ e_out,
            int E) {
    extern __shared__ float sm[];
    float* sE = sm;                             // 4352 floats
    float* sB = sm + 64 * SE_PITCH;             // alias region: 9216 floats
    float* sOut0 = sB;                          // 64*72 = 4608 (e_out acc)
    float* sOut1 = sB + 64 * SO_PITCH;          // 64*72 = 4608 (e1 acc)
    int* sSrc = (int*)(sB + 2 * 64 * SO_PITCH); // 64
    int* sDst = sSrc + 64;                      // 64

    int tid = threadIdx.x;
    int ebase = blockIdx.x * 64;
    int nE = E - ebase; if (nE > 64) nE = 64;

    // weights: vectorized float4 copy (2048 float4) into first 8192 of alias
    {
        const float4* gW = reinterpret_cast<const float4*>(g_Wmma);
        float4* sB4 = reinterpret_cast<float4*>(sB);
        #pragma unroll
        for (int it = 0; it < 8; it++)
            sB4[tid + it * 256] = gW[tid + it * 256];
    }

    // edge tile (64 x 64), edge-major
    #pragma unroll
    for (int it = 0; it < 4; it++) {
        int i = tid + it * 256;
        int e = i >> 4, q = i & 15;
        float4 v = (e < nE)
            ? reinterpret_cast<const float4*>(edge_in)[(size_t)(ebase + e) * 16 + q]
            : make_float4(0.f, 0.f, 0.f, 0.f);
        *reinterpret_cast<float4*>(&sE[e * SE_PITCH + 4 * q]) = v;
    }
    if (tid < 64) {
        sSrc[tid] = (tid < nE) ? src[ebase + tid] : 0;
        sDst[tid] = (tid < nE) ? dst[ebase + tid] : 0;
    }
    __syncthreads();

    if (tid < 64 && tid < nE) atomicAdd(g_deg + sDst[tid], 1.0f);

    int wid = tid >> 5, lane = tid & 31;
    int gid = lane >> 2, tig = lane & 3;
    int mw = wid & 3;            // m-tile (16 edges)
    int nhalf = wid >> 2;        // 0: n 0..31, 1: n 32..63
    int ew = mw * 16;

    // ---- dual tf32 mma: acc (e_out via We2e_top), acc2 (e1 via We2n) ----
    float acc[4][4], acc2[4][4];
    #pragma unroll
    for (int nt = 0; nt < 4; nt++) {
        acc[nt][0] = 0.f; acc[nt][1] = 0.f; acc[nt][2] = 0.f; acc[nt][3] = 0.f;
        acc2[nt][0] = 0.f; acc2[nt][1] = 0.f; acc2[nt][2] = 0.f; acc2[nt][3] = 0.f;
    }

    const float* rowA0 = &sE[(ew + gid) * SE_PITCH];
    const float* rowA1 = &sE[(ew + gid + 8) * SE_PITCH];
    #pragma unroll
    for (int ks = 0; ks < 8; ks++) {
        int k0 = ks * 8 + tig;
        uint32_t a0, a1, a2, a3;
        asm("cvt.rna.tf32.f32 %0, %1;" : "=r"(a0) : "f"(rowA0[k0]));
        asm("cvt.rna.tf32.f32 %0, %1;" : "=r"(a1) : "f"(rowA1[k0]));
        asm("cvt.rna.tf32.f32 %0, %1;" : "=r"(a2) : "f"(rowA0[k0 + 4]));
        asm("cvt.rna.tf32.f32 %0, %1;" : "=r"(a3) : "f"(rowA1[k0 + 4]));
        #pragma unroll
        for (int nt = 0; nt < 4; nt++) {
            int ntile = nhalf * 4 + nt;
            int boff = ((ks * 8 + ntile) * 32 + lane) * 2;
            float2 b = *reinterpret_cast<const float2*>(&sB[boff]);
            uint32_t b0 = __float_as_uint(b.x), b1 = __float_as_uint(b.y);
            asm volatile(
                "mma.sync.aligned.m16n8k8.row.col.f32.tf32.tf32.f32 "
                "{%0,%1,%2,%3}, {%4,%5,%6,%7}, {%8,%9}, {%0,%1,%2,%3};"
                : "+f"(acc[nt][0]), "+f"(acc[nt][1]),
                  "+f"(acc[nt][2]), "+f"(acc[nt][3])
                : "r"(a0), "r"(a1), "r"(a2), "r"(a3), "r"(b0), "r"(b1));
            float2 c = *reinterpret_cast<const float2*>(&sB[4096 + boff]);
            uint32_t c0 = __float_as_uint(c.x), c1 = __float_as_uint(c.y);
            asm volatile(
                "mma.sync.aligned.m16n8k8.row.col.f32.tf32.tf32.f32 "
                "{%0,%1,%2,%3}, {%4,%5,%6,%7}, {%8,%9}, {%0,%1,%2,%3};"
                : "+f"(acc2[nt][0]), "+f"(acc2[nt][1]),
                  "+f"(acc2[nt][2]), "+f"(acc2[nt][3])
                : "r"(a0), "r"(a1), "r"(a2), "r"(a3), "r"(c0), "r"(c1));
        }
    }
    __syncthreads();   // ALL warps done reading sB before aliasing writes

    // stage both accumulators into the alias region (pitch 72 -> 2-way max)
    {
        int e0 = ew + gid, e1r = ew + gid + 8;
        #pragma unroll
        for (int nt = 0; nt < 4; nt++) {
            int n = (nhalf * 4 + nt) * 8 + 2 * tig;
            *reinterpret_cast<float2*>(&sOut0[e0 * SO_PITCH + n]) =
                make_float2(acc[nt][0], acc[nt][1]);
            *reinterpret_cast<float2*>(&sOut0[e1r * SO_PITCH + n]) =
                make_float2(acc[nt][2], acc[nt][3]);
            *reinterpret_cast<float2*>(&sOut1[e0 * SO_PITCH + n]) =
                make_float2(acc2[nt][0], acc2[nt][1]);
            *reinterpret_cast<float2*>(&sOut1[e1r * SO_PITCH + n]) =
                make_float2(acc2[nt][2], acc2[nt][3]);
        }
    }
    __syncthreads();

    // ---- fused final pass: scatter RED(h1[src]+e1) + coalesced epilogue ----
    const float4* b4  = reinterpret_cast<const float4*>(bias_e);
    const float4* h14 = reinterpret_cast<const float4*>(g_h1);
    const float4* hu4 = reinterpret_cast<const float4*>(g_hu2);
    const float4* hv4 = reinterpret_cast<const float4*>(g_hv2);
    #pragma unroll
    for (int it = 0; it < 4; it++) {
        int i = tid + it * 256;
        int e = i >> 4, q = i & 15;
        if (e < nE) {
            int s = sSrc[e], d2 = sDst[e];
            // scatter: g_agg[dst] += h1[src] + e1
            float4 e1v = *reinterpret_cast<const float4*>(&sOut1[e * SO_PITCH + 4 * q]);
            float4 h1v = __ldg(h14 + (size_t)s * 16 + q);
            float* a = g_agg + (size_t)d2 * D + q * 4;
            asm volatile("red.global.add.v4.f32 [%0], {%1,%2,%3,%4};"
                         :: "l"(a),
                            "f"(h1v.x + e1v.x), "f"(h1v.y + e1v.y),
                            "f"(h1v.z + e1v.z), "f"(h1v.w + e1v.w)
                         : "memory");
            // epilogue: e_out = acc + hu2[src] + hv2[dst] + bias
            float4 av = *reinterpret_cast<const float4*>(&sOut0[e * SO_PITCH + 4 * q]);
            float4 hu = __ldg(hu4 + (size_t)s  * 16 + q);
            float4 hv = __ldg(hv4 + (size_t)d2 * 16 + q);
            float4 bb = __ldg(b4 + q);
            reinterpret_cast<float4*>(e_out)[(size_t)(ebase + e) * 16 + q] =
                make_float4(av.x + hu.x + hv.x + bb.x, av.y + hu.y + hv.y + bb.y,
                            av.z + hu.z + hv.z + bb.z, av.w + hu.w + hv.w + bb.w);
        }
    }
}

// ---------------------------------------------------------------------------
// K2: single-phase — hn comes straight from g_agg/deg:
//     h_out = S@Wv0 + X@Wv1 + (g_agg/max(deg,1))@Wv2 + bias_n
// ---------------------------------------------------------------------------
__global__ __launch_bounds__(256) void k_node_out(const float* __restrict__ S,
                                                  const float* __restrict__ X,
                                                  const float* __restrict__ Wv,
                                                  const float* __restrict__ bias_n,
                                                  float* __restrict__ h_out,
                                                  int N) {
    extern __shared__ float sm[];
    float (*sST)[65] = (float(*)[65])sm;                // 0..4160
    float (*sXT)[65] = (float(*)[65])(sm + 4160);       // ..8320
    float (*sHT)[65] = (float(*)[65])(sm + 8320);       // ..12480
    float* sWv = sm + 12480;                             // ..24768

    int tid = threadIdx.x;
    int base = blockIdx.x * 64;
    int nN = N - base; if (nN > 64) nN = 64;
    int tx = tid & 15, ty = tid >> 4;

    for (int i = tid; i < 3 * D * D; i += 256)
        sWv[i] = Wv[i];
    load_tile_T(sST, S, base, nN, tid);
    load_tile_T(sXT, X, base, nN, tid);
    // hn tile: load g_agg scaled by 1/max(deg,1), transposed
    #pragma unroll
    for (int it = 0; it < 4; it++) {
        int i = tid + it * 256;
        int n = i >> 4, q = i & 15;
        float4 v = make_float4(0.f, 0.f, 0.f, 0.f);
        if (n < nN) {
            v = reinterpret_cast<const float4*>(g_agg)[(size_t)(base + n) * 16 + q];
            float inv = 1.0f / fmaxf(g_deg[base + n], 1.0f);
            v.x *= inv; v.y *= inv; v.z *= inv; v.w *= inv;
        }
        sHT[4 * q + 0][n] = v.x;
        sHT[4 * q + 1][n] = v.y;
        sHT[4 * q + 2][n] = v.z;
        sHT[4 * q + 3][n] = v.w;
    }
    __syncthreads();

    float4 bb = reinterpret_cast<const float4*>(bias_n)[tx];
    float acc[4][4];
    #pragma unroll
    for (int r = 0; r < 4; r++) {
        acc[r][0] = bb.x; acc[r][1] = bb.y; acc[r][2] = bb.z; acc[r][3] = bb.w;
    }

    #pragma unroll 8
    for (int k = 0; k < D; k++) {
        float4 wS = *reinterpret_cast<const float4*>(&sWv[k * D + tx * 4]);
        float4 wX = *reinterpret_cast<const float4*>(&sWv[(D + k) * D + tx * 4]);
        float4 wH = *reinterpret_cast<const float4*>(&sWv[(2 * D + k) * D + tx * 4]);
        #pragma unroll
        for (int r = 0; r < 4; r++) {
            float s = sST[k][ty * 4 + r];
            float x = sXT[k][ty * 4 + r];
            float h = sHT[k][ty * 4 + r];
            acc[r][0] += s * wS.x + x * wX.x + h * wH.x;
            acc[r][1] += s * wS.y + x * wX.y + h * wH.y;
            acc[r][2] += s * wS.z + x * wX.z + h * wH.z;
            acc[r][3] += s * wS.w + x * wX.w + h * wH.w;
        }
    }

    #pragma unroll
    for (int r = 0; r < 4; r++) {
        int n = ty * 4 + r;
        if (n >= nN) continue;
        reinterpret_cast<float4*>(h_out)[(size_t)(base + n) * 16 + tx] =
            make_float4(acc[r][0], acc[r][1], acc[r][2], acc[r][3]);
    }
}

// ---------------------------------------------------------------------------
extern "C" void kernel_launch(void* const* d_in, const int* in_sizes, int n_in,
                              void* d_out, int out_size) {
    const float* S      = (const float*)d_in[0];
    const float* X      = (const float*)d_in[1];
    const float* Ein    = (const float*)d_in[2];
    const int*   src    = (const int*)d_in[3];
    const int*   dst    = (const int*)d_in[4];
    const float* Wn2n_u = (const float*)d_in[5];
    const float* Wn2n_v = (const float*)d_in[6];
    const float* We2n   = (const float*)d_in[7];
    const float* bias_n = (const float*)d_in[8];
    const float* Wn2e_u = (const float*)d_in[9];
    const float* Wn2e_v = (const float*)d_in[10];
    const float* We2e   = (const float*)d_in[11];
    const float* bias_e = (const float*)d_in[12];

    int N = in_sizes[1] / D;
    int E = in_sizes[3];
    float* h_out = (float*)d_out;
    float* e_out = h_out + (size_t)N * D;

    const int SM_PRE  = 24704 * 4;                                   // 98816 B
    const int SM_OUT  = 24768 * 4;                                   // 99072 B
    const int SM_EDGE = (64 * SE_PITCH + 2 * 64 * SO_PITCH) * 4
                        + 128 * 4;                                   // 54784 B

    cudaFuncSetAttribute(k_node_pre, cudaFuncAttributeMaxDynamicSharedMemorySize, SM_PRE);
    cudaFuncSetAttribute(k_node_out, cudaFuncAttributeMaxDynamicSharedMemorySize, SM_OUT);
    cudaFuncSetAttribute(k_edge,     cudaFuncAttributeMaxDynamicSharedMemorySize, SM_EDGE);

    int nBlk = (N + 63) / 64;
    k_zero<<<(N * D / 4 + 255) / 256, 256>>>(N);
    k_wprep<<<(3 * D * D + 2 * 2048 + 255) / 256, 256>>>(Wn2e_u, Wn2e_v, We2e, We2n);
    k_node_pre<<<nBlk, 256, SM_PRE>>>(S, X, Wn2n_u, N);
    k_edge<<<(E + 63) / 64, 256, SM_EDGE>>>(Ein, src, dst, bias_e, e_out, E);
    k_node_out<<<nBlk, 256, SM_OUT>>>(S, X, Wn2n_v, bias_n, h_out, N);
}